// round 6
// baseline (speedup 1.0000x reference)
#include <cuda_runtime.h>
#include <math.h>

#define MAXB 16384

// ---------------- device scratch (no allocations allowed) ----------------
__device__ unsigned g_w1[32];              // 27-bit key per oc, bit = c*9+dy*3+dx
__device__ int      g_T1[32];
__device__ unsigned g_w2[288];             // [oc*9 + dy*3+dx], bit = input channel
__device__ int      g_T2[32];
__device__ unsigned g_w3[576];             // [oc*9 + dy*3+dx], bit = input channel
__device__ int      g_T3[64];
__device__ unsigned g_fc1[256];            // [j*2 + half], bit k = sign(w_fc1[j][half*32+k])
__device__ float    g_a4[128], g_c4[128];  // bn4 folded: h = clamp(a*s + c)
__device__ float    g_head[12];            // a5[2], c5[2], a6[4], c6[4]

// ---------------- bn threshold helper ----------------
__device__ __forceinline__ double bn_thresh_t(const float* bn, int C, int c) {
    // bn rows: gamma, beta, mean, var.  sign(bn(s)) >= 0  <=>  s >= m - b*sqrt(v+eps)/g   (g > 0)
    double g = bn[c], b = bn[C + c], m = bn[2 * C + c], v = bn[3 * C + c];
    return m - b * sqrt(v + 1e-5) / g;
}

// ---------------- prep: weight packing + threshold folding (8 CTAs) ----------------
__global__ void prep_kernel(const float* __restrict__ w1, const float* __restrict__ w2,
                            const float* __restrict__ w3, const float* __restrict__ wfc1,
                            const float* __restrict__ bn1, const float* __restrict__ bn2,
                            const float* __restrict__ bn3, const float* __restrict__ bn4,
                            const float* __restrict__ bn5, const float* __restrict__ bn6) {
    const int t = blockIdx.x * 256 + threadIdx.x;
    const int nt = 8 * 256;
    for (int oc = t; oc < 32; oc += nt) {
        unsigned w = 0;
        for (int k = 0; k < 27; ++k) if (w1[oc * 27 + k] >= 0.f) w |= 1u << k;
        g_w1[oc] = w;
        g_T1[oc] = (int)floor((27.0 - bn_thresh_t(bn1, 32, oc)) * 0.5);   // keep iff cnt_disagree <= T
        g_T2[oc] = (int)floor((288.0 - bn_thresh_t(bn2, 32, oc)) * 0.5);
    }
    for (int i = t; i < 288; i += nt) {
        int oc = i / 9, p = i % 9; unsigned w = 0;
        for (int c = 0; c < 32; ++c) if (w2[(oc * 32 + c) * 9 + p] >= 0.f) w |= 1u << c;
        g_w2[i] = w;
    }
    for (int i = t; i < 576; i += nt) {
        int oc = i / 9, p = i % 9; unsigned w = 0;
        for (int c = 0; c < 32; ++c) if (w3[(oc * 32 + c) * 9 + p] >= 0.f) w |= 1u << c;
        g_w3[i] = w;
    }
    for (int oc = t; oc < 64; oc += nt)
        g_T3[oc] = (int)floor((288.0 - bn_thresh_t(bn3, 64, oc)) * 0.5);
    for (int i = t; i < 256; i += nt) {
        int j = i >> 1, h = i & 1; unsigned w = 0;
        for (int k = 0; k < 32; ++k) if (wfc1[j * 64 + h * 32 + k] >= 0.f) w |= 1u << k;
        g_fc1[i] = w;
    }
    for (int j = t; j < 128; j += nt) {
        float g = bn4[j], b = bn4[128 + j], m = bn4[256 + j], v = bn4[384 + j];
        float inv = g * rsqrtf(v + 1e-5f);
        g_a4[j] = inv; g_c4[j] = b - m * inv;
    }
    if (t < 2) {
        float g = bn5[t], b = bn5[2 + t], m = bn5[4 + t], v = bn5[6 + t];
        float inv = g * rsqrtf(v + 1e-5f);
        g_head[t] = inv; g_head[2 + t] = b - m * inv;
    }
    if (t >= 4 && t < 8) {
        int q = t - 4;
        float g = bn6[q], b = bn6[4 + q], m = bn6[8 + q], v = bn6[12 + q];
        float inv = g * rsqrtf(v + 1e-5f);
        g_head[4 + q] = inv; g_head[8 + q] = b - m * inv;
    }
}

// naive 9-word popcount sum starting from a base (base = ~T folds the threshold in)
__device__ __forceinline__ int popc9b(int base,
                                      unsigned x0, unsigned x1, unsigned x2,
                                      unsigned x3, unsigned x4, unsigned x5,
                                      unsigned x6, unsigned x7, unsigned x8) {
    return base + __popc(x0) + __popc(x1) + __popc(x2)
                + __popc(x3) + __popc(x4) + __popc(x5)
                + __popc(x6) + __popc(x7) + __popc(x8);
}

// ---------------- main fused network: 8 threads (an "octet") per sample ----------------
// Input binarize+pack via warp ballot; thresholds folded as base=~T; pooling via sign-OR.
__global__ void __launch_bounds__(128, 8) main_kernel(
    const float* __restrict__ x,
    const float* __restrict__ wfc2, const float* __restrict__ wfc3,
    float* __restrict__ out, int B) {

    __shared__ unsigned s_w1[32];  __shared__ int s_T1[32];
    __shared__ unsigned s_w2[288]; __shared__ int s_T2[32];
    __shared__ unsigned s_w3[576]; __shared__ int s_T3[64];
    __shared__ unsigned s_fc1[256];
    __shared__ float s_a4[128], s_c4[128];
    __shared__ float s_f2[256], s_f3[512];
    __shared__ float s_head[12];
    __shared__ unsigned s_pin[16][66];  // packed input rows per sample slot
    __shared__ unsigned s_s1[16][100];  // (a) ballot bitstream (46 words), then (b) stage-1 pooled bits
    __shared__ unsigned s_s2[16][16];   // stage-2 pooled bits, word (pr*4+pc), bit = oc

    const int tid = threadIdx.x;
    for (int i = tid; i < 32; i += 128) { s_w1[i] = g_w1[i]; s_T1[i] = g_T1[i]; s_T2[i] = g_T2[i]; }
    for (int i = tid; i < 288; i += 128) s_w2[i] = g_w2[i];
    for (int i = tid; i < 576; i += 128) s_w3[i] = g_w3[i];
    for (int i = tid; i < 64; i += 128) s_T3[i] = g_T3[i];
    for (int i = tid; i < 256; i += 128) { s_fc1[i] = g_fc1[i]; s_f2[i] = wfc2[i]; }
    for (int i = tid; i < 128; i += 128) { s_a4[i] = g_a4[i]; s_c4[i] = g_c4[i]; }
    for (int i = tid; i < 512; i += 128) s_f3[i] = wfc3[i];
    if (tid < 12) s_head[tid] = g_head[tid];
    __syncthreads();

    const int lane = tid & 31;
    const int base = blockIdx.x * 16;

    // ---- binarize + pack: each warp packs its 4 samples (coalesced loads + ballot) ----
    for (int ss = 0; ss < 4; ++ss) {
        int slot = (tid >> 5) * 4 + ss;
        int samp = base + slot;
        if (samp >= B) break;                       // uniform within warp
        const float* xs = x + (size_t)samp * 1452;
        unsigned* dst = s_s1[slot];                 // 46-word bitstream staging
        for (int j0 = 0; j0 < 46; j0 += 8) {
            float v[8];
#pragma unroll
            for (int k = 0; k < 8; ++k) {
                int idx = (j0 + k) * 32 + lane;
                v[k] = (idx < 1452) ? xs[idx] : -1.f;
            }
#pragma unroll
            for (int k = 0; k < 8; ++k) {
                unsigned b = __ballot_sync(0xFFFFFFFFu, v[k] >= 0.f);
                if (lane == k && (j0 + k) < 46) dst[j0 + k] = b;
            }
        }
    }
    __syncwarp();

    const int gt = blockIdx.x * 128 + tid;
    const int s = gt >> 3;        // sample
    const int r = gt & 7;         // lane within octet
    if (s >= B) return;           // B multiple of 16 -> whole warps exit together
    const int sl = tid >> 3;      // sample slot in CTA (0..15)

    // re-align bitstream to 22-bit row words: word i covers bits [22i, 22i+22)
    {
        const unsigned* st = s_s1[sl];
        for (int i = r; i < 66; i += 8) {
            int off = i * 22;
            s_pin[sl][i] = __funnelshift_r(st[off >> 5], st[(off >> 5) + 1], off & 31) & 0x3FFFFFu;
        }
    }
    __syncwarp();

    const unsigned* __restrict__ pin = s_pin[sl];
    unsigned* s1 = s_s1[sl];

    // ---- conv1 (27-term XNOR) + threshold + pool(sign-OR) -> s1[10][10], bit = oc ----
    for (int py = 0; py < 10; ++py) {
        unsigned rows[12];
#pragma unroll
        for (int c = 0; c < 3; ++c)
#pragma unroll
            for (int k = 0; k < 4; ++k) rows[c * 4 + k] = pin[c * 22 + 2 * py + k];
        // lane owns cells with (py*10+px) % 8 == r  ->  px ≡ (r + 6*py) (mod 8)
        int px0 = (r + 6 * py) & 7;
        for (int px = px0; px < 10; px += 8) {
            unsigned key[4];
#pragma unroll
            for (int yy = 0; yy < 2; ++yy)
#pragma unroll
                for (int xx = 0; xx < 2; ++xx) {
                    int x0 = 2 * px + xx;
                    unsigned k = 0;
#pragma unroll
                    for (int c = 0; c < 3; ++c)
#pragma unroll
                        for (int dy = 0; dy < 3; ++dy)
                            k |= ((rows[c * 4 + yy + dy] >> x0) & 7u) << (c * 9 + dy * 3);
                    key[yy * 2 + xx] = k;
                }
            unsigned acc = 0;
#pragma unroll
            for (int oc = 0; oc < 32; ++oc) {
                unsigned w = s_w1[oc];
                int nT = ~s_T1[oc];   // d = cnt - T - 1 < 0  <=>  cnt <= T
                int d0 = nT + __popc(key[0] ^ w);
                int d1 = nT + __popc(key[1] ^ w);
                int d2 = nT + __popc(key[2] ^ w);
                int d3 = nT + __popc(key[3] ^ w);
                unsigned neg = (unsigned)((d0 | d1) | (d2 | d3));   // sign set iff any d_i < 0
                acc |= (neg >> (31 - oc)) & (1u << oc);
            }
            s1[py * 10 + px] = acc;
        }
    }
    __syncwarp();

    // ---- conv2 (288-term): lane owns pooled row r>>1, 2 cells, all 32 oc ----
    {
        const int pr = r >> 1;            // 0..3
        const int pcb = (r & 1) * 2;      // 0 or 2
        unsigned R[4][6];                 // rows 2pr..2pr+3, cols 2*pcb .. 2*pcb+5
#pragma unroll
        for (int y = 0; y < 4; ++y)
#pragma unroll
            for (int xx = 0; xx < 6; ++xx) R[y][xx] = s1[(2 * pr + y) * 10 + 2 * pcb + xx];
        unsigned acc0 = 0u, acc1 = 0u;
#pragma unroll 4
        for (int oc = 0; oc < 32; ++oc) {
            unsigned w[9];
#pragma unroll
            for (int j = 0; j < 9; ++j) w[j] = s_w2[oc * 9 + j];
            int nT = ~s_T2[oc];
#pragma unroll
            for (int cell = 0; cell < 2; ++cell) {
                const int cb = 2 * cell;
                int d0 = popc9b(nT,
                                R[0][cb] ^ w[0], R[0][cb + 1] ^ w[1], R[0][cb + 2] ^ w[2],
                                R[1][cb] ^ w[3], R[1][cb + 1] ^ w[4], R[1][cb + 2] ^ w[5],
                                R[2][cb] ^ w[6], R[2][cb + 1] ^ w[7], R[2][cb + 2] ^ w[8]);
                int d1 = popc9b(nT,
                                R[0][cb + 1] ^ w[0], R[0][cb + 2] ^ w[1], R[0][cb + 3] ^ w[2],
                                R[1][cb + 1] ^ w[3], R[1][cb + 2] ^ w[4], R[1][cb + 3] ^ w[5],
                                R[2][cb + 1] ^ w[6], R[2][cb + 2] ^ w[7], R[2][cb + 3] ^ w[8]);
                int d2 = popc9b(nT,
                                R[1][cb] ^ w[0], R[1][cb + 1] ^ w[1], R[1][cb + 2] ^ w[2],
                                R[2][cb] ^ w[3], R[2][cb + 1] ^ w[4], R[2][cb + 2] ^ w[5],
                                R[3][cb] ^ w[6], R[3][cb + 1] ^ w[7], R[3][cb + 2] ^ w[8]);
                int d3 = popc9b(nT,
                                R[1][cb + 1] ^ w[0], R[1][cb + 2] ^ w[1], R[1][cb + 3] ^ w[2],
                                R[2][cb + 1] ^ w[3], R[2][cb + 2] ^ w[4], R[2][cb + 3] ^ w[5],
                                R[3][cb + 1] ^ w[6], R[3][cb + 2] ^ w[7], R[3][cb + 3] ^ w[8]);
                unsigned neg = (unsigned)((d0 | d1) | (d2 | d3));
                if (cell == 0) acc0 |= (neg >> (31 - oc)) & (1u << oc);
                else           acc1 |= (neg >> (31 - oc)) & (1u << oc);
            }
        }
        s_s2[sl][pr * 4 + pcb]     = acc0;
        s_s2[sl][pr * 4 + pcb + 1] = acc1;
    }
    __syncwarp();

    // ---- conv3 (288-term, 64 oc; 8 per lane) + pool(sign-OR) -> 64 bits (a0,a1) ----
    unsigned S2[16];
#pragma unroll
    for (int i = 0; i < 16; ++i) S2[i] = s_s2[sl][i];

    unsigned p0 = 0u, p1 = 0u;
    const int ocb3 = r * 8;
#pragma unroll 1
    for (int k = 0; k < 8; ++k) {
        int oc = ocb3 + k;
        unsigned w[9];
#pragma unroll
        for (int j = 0; j < 9; ++j) w[j] = s_w3[oc * 9 + j];
        int nT = ~s_T3[oc];
        int d0 = popc9b(nT, S2[0] ^ w[0], S2[1] ^ w[1], S2[2] ^ w[2],
                            S2[4] ^ w[3], S2[5] ^ w[4], S2[6] ^ w[5],
                            S2[8] ^ w[6], S2[9] ^ w[7], S2[10] ^ w[8]);
        int d1 = popc9b(nT, S2[1] ^ w[0], S2[2] ^ w[1], S2[3] ^ w[2],
                            S2[5] ^ w[3], S2[6] ^ w[4], S2[7] ^ w[5],
                            S2[9] ^ w[6], S2[10] ^ w[7], S2[11] ^ w[8]);
        int d2 = popc9b(nT, S2[4] ^ w[0], S2[5] ^ w[1], S2[6] ^ w[2],
                            S2[8] ^ w[3], S2[9] ^ w[4], S2[10] ^ w[5],
                            S2[12] ^ w[6], S2[13] ^ w[7], S2[14] ^ w[8]);
        int d3 = popc9b(nT, S2[5] ^ w[0], S2[6] ^ w[1], S2[7] ^ w[2],
                            S2[9] ^ w[3], S2[10] ^ w[4], S2[11] ^ w[5],
                            S2[13] ^ w[6], S2[14] ^ w[7], S2[15] ^ w[8]);
        unsigned neg = (unsigned)((d0 | d1) | (d2 | d3));
        int b = oc & 31;
        unsigned mbit = (neg >> (31 - b)) & (1u << b);
        if (r < 4) p0 |= mbit; else p1 |= mbit;
    }
    unsigned a0 = p0, a1 = p1;
    a0 |= __shfl_xor_sync(0xFFFFFFFFu, a0, 1); a0 |= __shfl_xor_sync(0xFFFFFFFFu, a0, 2);
    a0 |= __shfl_xor_sync(0xFFFFFFFFu, a0, 4);
    a1 |= __shfl_xor_sync(0xFFFFFFFFu, a1, 1); a1 |= __shfl_xor_sync(0xFFFFFFFFu, a1, 2);
    a1 |= __shfl_xor_sync(0xFFFFFFFFu, a1, 4);

    // ---- fc1 (binary 64-dot) + bn4 + hardtanh, fused with the two float heads ----
    float t0 = 0.f, t1 = 0.f, u0 = 0.f, u1 = 0.f, u2 = 0.f, u3 = 0.f;
    const int jb = r * 16;
#pragma unroll 4
    for (int k = 0; k < 16; ++k) {
        int j = jb + k;
        int cnt = __popc(a0 ^ s_fc1[2 * j]) + __popc(a1 ^ s_fc1[2 * j + 1]);
        float sv = (float)(64 - 2 * cnt);
        float h = fminf(1.f, fmaxf(-1.f, fmaf(sv, s_a4[j], s_c4[j])));
        t0 = fmaf(h, s_f2[j], t0);
        t1 = fmaf(h, s_f2[128 + j], t1);
        u0 = fmaf(h, s_f3[j], u0);
        u1 = fmaf(h, s_f3[128 + j], u1);
        u2 = fmaf(h, s_f3[256 + j], u2);
        u3 = fmaf(h, s_f3[384 + j], u3);
    }
#pragma unroll
    for (int d = 1; d < 8; d <<= 1) {
        t0 += __shfl_xor_sync(0xFFFFFFFFu, t0, d);
        t1 += __shfl_xor_sync(0xFFFFFFFFu, t1, d);
        u0 += __shfl_xor_sync(0xFFFFFFFFu, u0, d);
        u1 += __shfl_xor_sync(0xFFFFFFFFu, u1, d);
        u2 += __shfl_xor_sync(0xFFFFFFFFu, u2, d);
        u3 += __shfl_xor_sync(0xFFFFFFFFu, u3, d);
    }
    if (r == 0) {
        float z0 = fmaf(t0, s_head[0], s_head[2]);
        float z1 = fmaf(t1, s_head[1], s_head[3]);
        float mx = fmaxf(z0, z1);
        float e0 = expf(z0 - mx), e1 = expf(z1 - mx);
        float is = 1.f / (e0 + e1);
        out[2 * s]     = e0 * is;
        out[2 * s + 1] = e1 * is;
        float* o2 = out + (size_t)2 * B;
        o2[4 * s]     = fmaf(u0, s_head[4], s_head[8]);
        o2[4 * s + 1] = fmaf(u1, s_head[5], s_head[9]);
        o2[4 * s + 2] = fmaf(u2, s_head[6], s_head[10]);
        o2[4 * s + 3] = fmaf(u3, s_head[7], s_head[11]);
    }
}

// ---------------- launch ----------------
extern "C" void kernel_launch(void* const* d_in, const int* in_sizes, int n_in,
                              void* d_out, int out_size) {
    (void)n_in; (void)out_size;
    const float* x    = (const float*)d_in[0];
    const float* w1   = (const float*)d_in[1];
    const float* w2   = (const float*)d_in[2];
    const float* w3   = (const float*)d_in[3];
    const float* wfc1 = (const float*)d_in[4];
    const float* wfc2 = (const float*)d_in[5];
    const float* wfc3 = (const float*)d_in[6];
    const float* bn1  = (const float*)d_in[7];
    const float* bn2  = (const float*)d_in[8];
    const float* bn3  = (const float*)d_in[9];
    const float* bn4  = (const float*)d_in[10];
    const float* bn5  = (const float*)d_in[11];
    const float* bn6  = (const float*)d_in[12];

    int B = in_sizes[0] / 1452;  // 3*22*22
    if (B > MAXB) B = MAXB;

    prep_kernel<<<8, 256>>>(w1, w2, w3, wfc1, bn1, bn2, bn3, bn4, bn5, bn6);
    main_kernel<<<(B * 8 + 127) / 128, 128>>>(x, wfc2, wfc3, (float*)d_out, B);
}

// round 7
// speedup vs baseline: 1.3192x; 1.3192x over previous
#include <cuda_runtime.h>
#include <math.h>

#define MAXB 16384

// ---------------- device scratch (no allocations allowed) ----------------
__device__ unsigned g_lut[3 * 512 * 7];    // [ (ch*512+key)*7 + g ]: five 6-bit slots/word, slot j -> oc=5g+j
__device__ unsigned g_w2[288];             // [oc*9 + dy*3+dx], bit = input channel
__device__ int      g_T2[32];
__device__ unsigned g_w3[576];             // [oc*9 + dy*3+dx], bit = input channel
__device__ int      g_T3[64];
__device__ unsigned g_fc1[256];            // [j*2 + half], bit k = sign(w_fc1[j][half*32+k])
__device__ float    g_a4[128], g_c4[128];  // bn4 folded: h = clamp(a*s + c)
__device__ float    g_head[12];            // a5[2], c5[2], a6[4], c6[4]

// ---------------- bn threshold helper ----------------
__device__ __forceinline__ double bn_thresh_t(const float* bn, int C, int c) {
    // bn rows: gamma, beta, mean, var.  sign(bn(s)) >= 0  <=>  s >= m - b*sqrt(v+eps)/g   (g > 0)
    double g = bn[c], b = bn[C + c], m = bn[2 * C + c], v = bn[3 * C + c];
    return m - b * sqrt(v + 1e-5) / g;
}

// ---------------- prep: weight packing + thresholds + conv1 LUT (8 CTAs) ----------------
__global__ void prep_kernel(const float* __restrict__ w1, const float* __restrict__ w2,
                            const float* __restrict__ w3, const float* __restrict__ wfc1,
                            const float* __restrict__ bn1, const float* __restrict__ bn2,
                            const float* __restrict__ bn3, const float* __restrict__ bn4,
                            const float* __restrict__ bn5, const float* __restrict__ bn6) {
    __shared__ unsigned s_wc[96];   // [ch*32+oc]: 9-bit channel slice of w1
    __shared__ int      s_off[32];  // 31 - clamp(T1, -5, 31)

    const int t = blockIdx.x * 256 + threadIdx.x;
    const int nt = 8 * 256;

    if (threadIdx.x < 96) {
        int ch = threadIdx.x / 32, oc = threadIdx.x & 31;
        unsigned w = 0;
        for (int k = 0; k < 9; ++k)
            if (w1[oc * 27 + ch * 9 + k] >= 0.f) w |= 1u << k;
        s_wc[threadIdx.x] = w;
    }
    if (threadIdx.x < 32) {
        int oc = threadIdx.x;
        int T = (int)floor((27.0 - bn_thresh_t(bn1, 32, oc)) * 0.5);  // keep iff cnt <= T
        if (T < -5) T = -5;
        if (T > 31) T = 31;
        s_off[oc] = 31 - T;   // reject iff cnt + off >= 32
    }
    __syncthreads();

    // conv1 LUT: 1536 records of 7 words
    for (int i = t; i < 1536; i += nt) {
        int ch = i / 512, key = i & 511;
        for (int g = 0; g < 7; ++g) {
            unsigned word = 0;
            for (int j = 0; j < 5; ++j) {
                int oc = 5 * g + j;
                if (oc < 32) {
                    unsigned f = (unsigned)__popc((key ^ s_wc[ch * 32 + oc]) & 0x1FF);
                    if (ch == 2) f += (unsigned)s_off[oc];
                    word |= f << (6 * j);
                }
            }
            g_lut[(ch * 512 + key) * 7 + g] = word;
        }
    }

    for (int oc = t; oc < 32; oc += nt)
        g_T2[oc] = (int)floor((288.0 - bn_thresh_t(bn2, 32, oc)) * 0.5);
    for (int i = t; i < 288; i += nt) {
        int oc = i / 9, p = i % 9; unsigned w = 0;
        for (int c = 0; c < 32; ++c) if (w2[(oc * 32 + c) * 9 + p] >= 0.f) w |= 1u << c;
        g_w2[i] = w;
    }
    for (int i = t; i < 576; i += nt) {
        int oc = i / 9, p = i % 9; unsigned w = 0;
        for (int c = 0; c < 32; ++c) if (w3[(oc * 32 + c) * 9 + p] >= 0.f) w |= 1u << c;
        g_w3[i] = w;
    }
    for (int oc = t; oc < 64; oc += nt)
        g_T3[oc] = (int)floor((288.0 - bn_thresh_t(bn3, 64, oc)) * 0.5);
    for (int i = t; i < 256; i += nt) {
        int j = i >> 1, h = i & 1; unsigned w = 0;
        for (int k = 0; k < 32; ++k) if (wfc1[j * 64 + h * 32 + k] >= 0.f) w |= 1u << k;
        g_fc1[i] = w;
    }
    for (int j = t; j < 128; j += nt) {
        float g = bn4[j], b = bn4[128 + j], m = bn4[256 + j], v = bn4[384 + j];
        float inv = g * rsqrtf(v + 1e-5f);
        g_a4[j] = inv; g_c4[j] = b - m * inv;
    }
    if (t < 2) {
        float g = bn5[t], b = bn5[2 + t], m = bn5[4 + t], v = bn5[6 + t];
        float inv = g * rsqrtf(v + 1e-5f);
        g_head[t] = inv; g_head[2 + t] = b - m * inv;
    }
    if (t >= 4 && t < 8) {
        int q = t - 4;
        float g = bn6[q], b = bn6[4 + q], m = bn6[8 + q], v = bn6[12 + q];
        float inv = g * rsqrtf(v + 1e-5f);
        g_head[4 + q] = inv; g_head[8 + q] = b - m * inv;
    }
}

// naive 9-word popcount sum
__device__ __forceinline__ int popc9(unsigned x0, unsigned x1, unsigned x2,
                                     unsigned x3, unsigned x4, unsigned x5,
                                     unsigned x6, unsigned x7, unsigned x8) {
    return __popc(x0) + __popc(x1) + __popc(x2)
         + __popc(x3) + __popc(x4) + __popc(x5)
         + __popc(x6) + __popc(x7) + __popc(x8);
}

// dynamic smem word offsets
#define SM_LUT  0                       // 10752 words
#define SM_PIN  10752                   // 16*66 = 1056
#define SM_S1   11808                   // 16*100 = 1600
#define SM_W2   13408                   // 288
#define SM_T2   13696                   // 32
#define SM_FC1  13728                   // 256
#define SM_WORDS 13984                  // 55936 bytes

// ---------------- main fused network: 8 threads (an "octet") per sample ----------------
__global__ void __launch_bounds__(128, 4) main_kernel(
    const float* __restrict__ x,
    const float* __restrict__ wfc2, const float* __restrict__ wfc3,
    float* __restrict__ out, int B) {

    extern __shared__ unsigned sm[];
    unsigned* s_lut = sm + SM_LUT;
    unsigned* s_w2  = sm + SM_W2;
    int*      s_T2  = (int*)(sm + SM_T2);
    unsigned* s_fc1 = sm + SM_FC1;

    const int tid = threadIdx.x;
    for (int i = tid; i < 10752; i += 128) s_lut[i] = g_lut[i];
    for (int i = tid; i < 288; i += 128) s_w2[i] = g_w2[i];
    for (int i = tid; i < 32; i += 128) s_T2[i] = g_T2[i];
    for (int i = tid; i < 256; i += 128) s_fc1[i] = g_fc1[i];
    __syncthreads();

    const int lane = tid & 31;
    const int base = blockIdx.x * 16;

    // ---- binarize + pack: each warp packs its 4 samples (coalesced loads + ballot) ----
    for (int ss = 0; ss < 4; ++ss) {
        int slot = (tid >> 5) * 4 + ss;
        int samp = base + slot;
        if (samp >= B) break;                       // uniform within warp
        const float* xs = x + (size_t)samp * 1452;
        unsigned* dst = sm + SM_S1 + slot * 100;    // 46-word bitstream staging
        for (int j0 = 0; j0 < 46; j0 += 8) {
            float v[8];
#pragma unroll
            for (int k = 0; k < 8; ++k) {
                int idx = (j0 + k) * 32 + lane;
                v[k] = (idx < 1452) ? xs[idx] : -1.f;
            }
#pragma unroll
            for (int k = 0; k < 8; ++k) {
                unsigned b = __ballot_sync(0xFFFFFFFFu, v[k] >= 0.f);
                if (lane == k && (j0 + k) < 46) dst[j0 + k] = b;
            }
        }
    }
    __syncwarp();

    const int gt = blockIdx.x * 128 + tid;
    const int s = gt >> 3;        // sample
    const int r = gt & 7;         // lane within octet
    if (s >= B) return;           // B multiple of 16 -> whole warps exit together
    const int sl = tid >> 3;      // sample slot in CTA (0..15)

    unsigned* pinw = sm + SM_PIN + sl * 66;
    unsigned* s1   = sm + SM_S1 + sl * 100;

    // re-align bitstream to 22-bit row words: word i covers bits [22i, 22i+22)
    {
        const unsigned* st = s1;
        for (int i = r; i < 66; i += 8) {
            int off = i * 22;
            pinw[i] = __funnelshift_r(st[off >> 5], st[(off >> 5) + 1], off & 31) & 0x3FFFFFu;
        }
    }
    __syncwarp();

    const unsigned* __restrict__ pin = pinw;

    // ---- conv1 via SWAR LUT + threshold + pool -> s1[10][10], bit = oc ----
    for (int py = 0; py < 10; ++py) {
        unsigned rows[12];
#pragma unroll
        for (int c = 0; c < 3; ++c)
#pragma unroll
            for (int k = 0; k < 4; ++k) rows[c * 4 + k] = pin[c * 22 + 2 * py + k];
        // lane owns cells with (py*10+px) % 8 == r  ->  px ≡ (r + 6*py) (mod 8)
        int px0 = (r + 6 * py) & 7;
        for (int px = px0; px < 10; px += 8) {
            unsigned Aw[7];
#pragma unroll
            for (int g = 0; g < 7; ++g) Aw[g] = 0xFFFFFFFFu;
#pragma unroll
            for (int yy = 0; yy < 2; ++yy)
#pragma unroll
                for (int xx = 0; xx < 2; ++xx) {
                    int x0 = 2 * px + xx;
                    const unsigned *L0, *L1, *L2;
                    {
                        unsigned k0 = ((rows[0 + yy] >> x0) & 7u)
                                    | (((rows[1 + yy] >> x0) & 7u) << 3)
                                    | (((rows[2 + yy] >> x0) & 7u) << 6);
                        unsigned k1 = ((rows[4 + yy] >> x0) & 7u)
                                    | (((rows[5 + yy] >> x0) & 7u) << 3)
                                    | (((rows[6 + yy] >> x0) & 7u) << 6);
                        unsigned k2 = ((rows[8 + yy] >> x0) & 7u)
                                    | (((rows[9 + yy] >> x0) & 7u) << 3)
                                    | (((rows[10 + yy] >> x0) & 7u) << 6);
                        L0 = s_lut + k0 * 7;
                        L1 = s_lut + (512 + k1) * 7;
                        L2 = s_lut + (1024 + k2) * 7;
                    }
#pragma unroll
                    for (int g = 0; g < 7; ++g)
                        Aw[g] &= L0[g] + L1[g] + L2[g];   // per-slot: cnt + (31-T); bit5 = reject
                }
            unsigned acc = 0;
#pragma unroll
            for (int g = 0; g < 7; ++g) {
                unsigned xb = (~Aw[g] & 0x20820820u) >> 5;   // keep bits at 0,6,12,18,24
                unsigned y = (xb * 0x108421u) >> 20;          // compress to 5 consecutive bits
                acc |= (y & 31u) << (5 * g);                  // g=6: bits>=32 drop (oc 30,31 ok)
            }
            s1[py * 10 + px] = acc;
        }
    }
    __syncwarp();

    // ---- conv2 (288-term): lane owns pooled row r>>1, 2 cells, all 32 oc ----
    // s2 staged into the (now dead) pin area: pinw[0..15]
    {
        const int pr = r >> 1;            // 0..3
        const int pcb = (r & 1) * 2;      // 0 or 2
        unsigned R[4][6];                 // rows 2pr..2pr+3, cols 2*pcb .. 2*pcb+5
#pragma unroll
        for (int y = 0; y < 4; ++y)
#pragma unroll
            for (int xx = 0; xx < 6; ++xx) R[y][xx] = s1[(2 * pr + y) * 10 + 2 * pcb + xx];
        unsigned acc0 = 0u, acc1 = 0u;
#pragma unroll 2
        for (int oc = 0; oc < 32; ++oc) {
            unsigned w[9];
#pragma unroll
            for (int j = 0; j < 9; ++j) w[j] = s_w2[oc * 9 + j];
            int T = s_T2[oc];
#pragma unroll
            for (int cell = 0; cell < 2; ++cell) {
                const int cb = 2 * cell;
                int c0 = popc9(R[0][cb] ^ w[0], R[0][cb + 1] ^ w[1], R[0][cb + 2] ^ w[2],
                               R[1][cb] ^ w[3], R[1][cb + 1] ^ w[4], R[1][cb + 2] ^ w[5],
                               R[2][cb] ^ w[6], R[2][cb + 1] ^ w[7], R[2][cb + 2] ^ w[8]);
                int c1 = popc9(R[0][cb + 1] ^ w[0], R[0][cb + 2] ^ w[1], R[0][cb + 3] ^ w[2],
                               R[1][cb + 1] ^ w[3], R[1][cb + 2] ^ w[4], R[1][cb + 3] ^ w[5],
                               R[2][cb + 1] ^ w[6], R[2][cb + 2] ^ w[7], R[2][cb + 3] ^ w[8]);
                int c2 = popc9(R[1][cb] ^ w[0], R[1][cb + 1] ^ w[1], R[1][cb + 2] ^ w[2],
                               R[2][cb] ^ w[3], R[2][cb + 1] ^ w[4], R[2][cb + 2] ^ w[5],
                               R[3][cb] ^ w[6], R[3][cb + 1] ^ w[7], R[3][cb + 2] ^ w[8]);
                int c3 = popc9(R[1][cb + 1] ^ w[0], R[1][cb + 2] ^ w[1], R[1][cb + 3] ^ w[2],
                               R[2][cb + 1] ^ w[3], R[2][cb + 2] ^ w[4], R[2][cb + 3] ^ w[5],
                               R[3][cb + 1] ^ w[6], R[3][cb + 2] ^ w[7], R[3][cb + 3] ^ w[8]);
                int m = min(min(c0, c1), min(c2, c3));
                if (cell == 0) acc0 |= (m <= T) ? (1u << oc) : 0u;
                else           acc1 |= (m <= T) ? (1u << oc) : 0u;
            }
        }
        pinw[pr * 4 + pcb]     = acc0;
        pinw[pr * 4 + pcb + 1] = acc1;
    }
    __syncwarp();

    // ---- conv3 (288-term, 64 oc; 8 per lane) + pool -> 64 bits (a0,a1) ----
    unsigned S2[16];
#pragma unroll
    for (int i = 0; i < 16; ++i) S2[i] = pinw[i];

    unsigned p0 = 0u, p1 = 0u;
    const int ocb3 = r * 8;
#pragma unroll 1
    for (int k = 0; k < 8; ++k) {
        int oc = ocb3 + k;
        unsigned w[9];
#pragma unroll
        for (int j = 0; j < 9; ++j) w[j] = __ldg(&g_w3[oc * 9 + j]);
        int T = __ldg(&g_T3[oc]);
        int c0 = popc9(S2[0] ^ w[0], S2[1] ^ w[1], S2[2] ^ w[2],
                       S2[4] ^ w[3], S2[5] ^ w[4], S2[6] ^ w[5],
                       S2[8] ^ w[6], S2[9] ^ w[7], S2[10] ^ w[8]);
        int c1 = popc9(S2[1] ^ w[0], S2[2] ^ w[1], S2[3] ^ w[2],
                       S2[5] ^ w[3], S2[6] ^ w[4], S2[7] ^ w[5],
                       S2[9] ^ w[6], S2[10] ^ w[7], S2[11] ^ w[8]);
        int c2 = popc9(S2[4] ^ w[0], S2[5] ^ w[1], S2[6] ^ w[2],
                       S2[8] ^ w[3], S2[9] ^ w[4], S2[10] ^ w[5],
                       S2[12] ^ w[6], S2[13] ^ w[7], S2[14] ^ w[8]);
        int c3 = popc9(S2[5] ^ w[0], S2[6] ^ w[1], S2[7] ^ w[2],
                       S2[9] ^ w[3], S2[10] ^ w[4], S2[11] ^ w[5],
                       S2[13] ^ w[6], S2[14] ^ w[7], S2[15] ^ w[8]);
        int m = min(min(c0, c1), min(c2, c3));
        unsigned mbit = (m <= T) ? (1u << (oc & 31)) : 0u;
        if (r < 4) p0 |= mbit; else p1 |= mbit;
    }
    unsigned a0 = p0, a1 = p1;
    a0 |= __shfl_xor_sync(0xFFFFFFFFu, a0, 1); a0 |= __shfl_xor_sync(0xFFFFFFFFu, a0, 2);
    a0 |= __shfl_xor_sync(0xFFFFFFFFu, a0, 4);
    a1 |= __shfl_xor_sync(0xFFFFFFFFu, a1, 1); a1 |= __shfl_xor_sync(0xFFFFFFFFu, a1, 2);
    a1 |= __shfl_xor_sync(0xFFFFFFFFu, a1, 4);

    // ---- fc1 (binary 64-dot) + bn4 + hardtanh, fused with the two float heads ----
    float t0 = 0.f, t1 = 0.f, u0 = 0.f, u1 = 0.f, u2 = 0.f, u3 = 0.f;
    const int jb = r * 16;
#pragma unroll 4
    for (int k = 0; k < 16; ++k) {
        int j = jb + k;
        int cnt = __popc(a0 ^ s_fc1[2 * j]) + __popc(a1 ^ s_fc1[2 * j + 1]);
        float sv = (float)(64 - 2 * cnt);
        float h = fminf(1.f, fmaxf(-1.f, fmaf(sv, __ldg(&g_a4[j]), __ldg(&g_c4[j]))));
        t0 = fmaf(h, __ldg(&wfc2[j]), t0);
        t1 = fmaf(h, __ldg(&wfc2[128 + j]), t1);
        u0 = fmaf(h, __ldg(&wfc3[j]), u0);
        u1 = fmaf(h, __ldg(&wfc3[128 + j]), u1);
        u2 = fmaf(h, __ldg(&wfc3[256 + j]), u2);
        u3 = fmaf(h, __ldg(&wfc3[384 + j]), u3);
    }
#pragma unroll
    for (int d = 1; d < 8; d <<= 1) {
        t0 += __shfl_xor_sync(0xFFFFFFFFu, t0, d);
        t1 += __shfl_xor_sync(0xFFFFFFFFu, t1, d);
        u0 += __shfl_xor_sync(0xFFFFFFFFu, u0, d);
        u1 += __shfl_xor_sync(0xFFFFFFFFu, u1, d);
        u2 += __shfl_xor_sync(0xFFFFFFFFu, u2, d);
        u3 += __shfl_xor_sync(0xFFFFFFFFu, u3, d);
    }
    if (r == 0) {
        float z0 = fmaf(t0, g_head[0], g_head[2]);
        float z1 = fmaf(t1, g_head[1], g_head[3]);
        float mx = fmaxf(z0, z1);
        float e0 = expf(z0 - mx), e1 = expf(z1 - mx);
        float is = 1.f / (e0 + e1);
        out[2 * s]     = e0 * is;
        out[2 * s + 1] = e1 * is;
        float* o2 = out + (size_t)2 * B;
        o2[4 * s]     = fmaf(u0, g_head[4], g_head[8]);
        o2[4 * s + 1] = fmaf(u1, g_head[5], g_head[9]);
        o2[4 * s + 2] = fmaf(u2, g_head[6], g_head[10]);
        o2[4 * s + 3] = fmaf(u3, g_head[7], g_head[11]);
    }
}

// ---------------- launch ----------------
extern "C" void kernel_launch(void* const* d_in, const int* in_sizes, int n_in,
                              void* d_out, int out_size) {
    (void)n_in; (void)out_size;
    const float* x    = (const float*)d_in[0];
    const float* w1   = (const float*)d_in[1];
    const float* w2   = (const float*)d_in[2];
    const float* w3   = (const float*)d_in[3];
    const float* wfc1 = (const float*)d_in[4];
    const float* wfc2 = (const float*)d_in[5];
    const float* wfc3 = (const float*)d_in[6];
    const float* bn1  = (const float*)d_in[7];
    const float* bn2  = (const float*)d_in[8];
    const float* bn3  = (const float*)d_in[9];
    const float* bn4  = (const float*)d_in[10];
    const float* bn5  = (const float*)d_in[11];
    const float* bn6  = (const float*)d_in[12];

    int B = in_sizes[0] / 1452;  // 3*22*22
    if (B > MAXB) B = MAXB;

    cudaFuncSetAttribute(main_kernel, cudaFuncAttributeMaxDynamicSharedMemorySize,
                         SM_WORDS * (int)sizeof(unsigned));

    prep_kernel<<<8, 256>>>(w1, w2, w3, wfc1, bn1, bn2, bn3, bn4, bn5, bn6);
    main_kernel<<<(B * 8 + 127) / 128, 128, SM_WORDS * sizeof(unsigned)>>>(
        x, wfc2, wfc3, (float*)d_out, B);
}